// round 1
// baseline (speedup 1.0000x reference)
#include <cuda_runtime.h>
#include <math.h>

#define B_ 8192
#define D_ 128

// Scratch (no allocations allowed): transposed scaled embeddings + per-row meta + sums.
__device__ float g_eT[D_ * B_];   // [k][row], value = e_hat * sqrt(log2(e)/T)
__device__ float g_lab[B_];       // +1 / -1
__device__ float g_sgn[B_];       // sign(conf): +1 / -1 / 0
__device__ float g_pos[B_];
__device__ float g_neg[B_];

// ---------------------------------------------------------------------------
// Kernel 1: normalize rows, fold in sqrt(log2e/T), write transposed, zero sums.
// One warp per row. 8 warps per block.
// ---------------------------------------------------------------------------
__global__ void prep_kernel(const float* __restrict__ emb,
                            const int*   __restrict__ labels,
                            const float* __restrict__ conf) {
    int row  = blockIdx.x * 8 + (threadIdx.x >> 5);
    int lane = threadIdx.x & 31;
    float4 v = ((const float4*)(emb + row * D_))[lane];
    float ss = v.x*v.x + v.y*v.y + v.z*v.z + v.w*v.w;
    #pragma unroll
    for (int o = 16; o; o >>= 1) ss += __shfl_xor_sync(0xffffffffu, ss, o);
    const float SCALE = 3.7982826f;   // sqrt(log2(e) / 0.1)
    float s = SCALE / fmaxf(sqrtf(ss), 1e-12f);
    int k = lane * 4;
    g_eT[(k+0)*B_ + row] = v.x * s;
    g_eT[(k+1)*B_ + row] = v.y * s;
    g_eT[(k+2)*B_ + row] = v.z * s;
    g_eT[(k+3)*B_ + row] = v.w * s;
    if (lane == 0) {
        g_lab[row] = (float)(2 * labels[row] - 1);
        float c = conf[row];
        g_sgn[row] = (c > 0.f) ? 1.f : ((c < 0.f) ? -1.f : 0.f);
        g_pos[row] = 0.f;
        g_neg[row] = 0.f;
    }
}

// ---------------------------------------------------------------------------
// Kernel 2: fused 64x64-tile sim GEMM + exp2 + masked row-sum accumulation.
// 256 threads, each computes a 4x4 micro-tile. Panels stored [k][row] so:
//   - fills: coalesced LDG.128 from g_eT + conflict-free STS.128
//   - frag loads: A broadcast LDS.128, B contiguous LDS.128 (conflict-free)
// ---------------------------------------------------------------------------
__global__ void __launch_bounds__(256, 4) sim_kernel() {
    __shared__ float As[64][64];   // [k - kk][row within i-tile]
    __shared__ float Bs[64][64];   // [k - kk][row within j-tile]
    __shared__ float meta[4][64];  // 0:labA 1:sgnA 2:labB 3:sgnB

    const int i0 = blockIdx.y * 64;
    const int j0 = blockIdx.x * 64;
    const int tid = threadIdx.x;
    const int tx = tid & 15;       // column group (4 cols each)
    const int ty = tid >> 4;       // row group (4 rows each)

    if (tid < 64)        { meta[0][tid]    = g_lab[i0 + tid];  meta[1][tid]    = g_sgn[i0 + tid]; }
    else if (tid < 128)  { int t = tid-64; meta[2][t] = g_lab[j0 + t]; meta[3][t] = g_sgn[j0 + t]; }

    float acc[4][4] = {};

    for (int kk = 0; kk < D_; kk += 64) {
        __syncthreads();
        #pragma unroll
        for (int t = tid; t < 1024; t += 256) {
            int k  = t >> 4;
            int r4 = (t & 15) << 2;
            const float* rowp = g_eT + (kk + k) * B_;
            *(float4*)&As[k][r4] = *(const float4*)(rowp + i0 + r4);
            *(float4*)&Bs[k][r4] = *(const float4*)(rowp + j0 + r4);
        }
        __syncthreads();
        #pragma unroll 16
        for (int k = 0; k < 64; k++) {
            float4 a4 = *(const float4*)&As[k][ty * 4];
            float4 b4 = *(const float4*)&Bs[k][tx * 4];
            float a[4] = {a4.x, a4.y, a4.z, a4.w};
            float b[4] = {b4.x, b4.y, b4.z, b4.w};
            #pragma unroll
            for (int r = 0; r < 4; r++)
                #pragma unroll
                for (int c = 0; c < 4; c++)
                    acc[r][c] = fmaf(a[r], b[c], acc[r][c]);
        }
    }

    // Epilogue: exp2(acc) already equals exp(sim/T). Apply masks, reduce per row.
    float la[4], sa[4], lb[4], sb[4];
    #pragma unroll
    for (int r = 0; r < 4; r++) { la[r] = meta[0][ty*4+r]; sa[r] = meta[1][ty*4+r]; }
    #pragma unroll
    for (int c = 0; c < 4; c++) { lb[c] = meta[2][tx*4+c]; sb[c] = meta[3][tx*4+c]; }

    #pragma unroll
    for (int r = 0; r < 4; r++) {
        int gi = i0 + ty*4 + r;
        float ps = 0.f, ns = 0.f;
        #pragma unroll
        for (int c = 0; c < 4; c++) {
            int gj = j0 + tx*4 + c;
            float ex = exp2f(acc[r][c]);
            if (sa[r] * sb[c] > 0.f) {
                if (la[r] == lb[c]) { if (gi != gj) ps += ex; }
                else                 ns += ex;
            }
        }
        #pragma unroll
        for (int o = 8; o; o >>= 1) {
            ps += __shfl_down_sync(0xffffffffu, ps, o, 16);
            ns += __shfl_down_sync(0xffffffffu, ns, o, 16);
        }
        if (tx == 0) {
            atomicAdd(&g_pos[gi], ps);
            atomicAdd(&g_neg[gi], ns);
        }
    }
}

// ---------------------------------------------------------------------------
// Kernel 3: final loss reduction over rows.
// ---------------------------------------------------------------------------
__global__ void loss_kernel(float* __restrict__ out, int B) {
    __shared__ float ssum[256];
    __shared__ float scnt[256];
    int tid = threadIdx.x;
    float tot = 0.f, cnt = 0.f;
    for (int i = tid; i < B; i += 256) {
        float p = g_pos[i], n = g_neg[i];
        if (p > 0.f && n > 0.f) {
            tot += -logf(p / (p + n + 1e-8f));
            cnt += 1.f;
        }
    }
    ssum[tid] = tot; scnt[tid] = cnt;
    __syncthreads();
    #pragma unroll
    for (int s = 128; s > 0; s >>= 1) {
        if (tid < s) { ssum[tid] += ssum[tid + s]; scnt[tid] += scnt[tid + s]; }
        __syncthreads();
    }
    if (tid == 0) {
        float c = scnt[0];
        out[0] = (c > 0.f) ? (ssum[0] / c) : 0.f;
    }
}

extern "C" void kernel_launch(void* const* d_in, const int* in_sizes, int n_in,
                              void* d_out, int out_size) {
    const float* emb    = (const float*)d_in[0];
    const int*   labels = (const int*)  d_in[1];
    const float* conf   = (const float*)d_in[2];
    int B = in_sizes[1];   // 8192
    (void)n_in; (void)out_size;

    prep_kernel<<<B / 8, 256>>>(emb, labels, conf);
    dim3 grid(B / 64, B / 64);
    sim_kernel<<<grid, 256>>>();
    loss_kernel<<<1, 256>>>((float*)d_out, B);
}

// round 3
// speedup vs baseline: 3.2571x; 3.2571x over previous
#include <cuda_runtime.h>
#include <math.h>
#include <stdint.h>

#define B_ 8192
#define D_ 128
#define NT_ 64              // number of 128-row tiles
#define NPAIRS ((NT_ * (NT_ + 1)) / 2)   // 2080 upper-triangular tile pairs

// Chunked smem tiles: 128 rows x 64 k, padded stride 68 floats.
#define LDS_ 68
#define TILE_BYTES (128 * LDS_ * 4)      // 34816
#define OFF_A0 0
#define OFF_B0 (TILE_BYTES)
#define OFF_A1 (2 * TILE_BYTES)
#define OFF_B1 (3 * TILE_BYTES)
#define OFF_QI (4 * TILE_BYTES)          // 139264
#define OFF_QJ (OFF_QI + 512)
#define SMEM_BYTES (OFF_QJ + 512)        // 140288

__device__ float g_eTF[B_ * D_];   // row-major, tf32-rounded, scaled by sqrt(log2e/T)
__device__ float g_q[B_];          // class code: sign(conf) * (label==1 ? 1 : 2)
__device__ float g_pos[B_];
__device__ float g_neg[B_];

// ---------------------------------------------------------------------------
__device__ __forceinline__ uint32_t smem_u32(const void* p) {
    uint32_t a;
    asm("{ .reg .u64 t; cvta.to.shared.u64 t, %1; cvt.u32.u64 %0, t; }" : "=r"(a) : "l"(p));
    return a;
}
__device__ __forceinline__ float tf32r(float x) {
    float y; asm("cvt.rna.tf32.f32 %0, %1;" : "=f"(y) : "f"(x)); return y;
}
__device__ __forceinline__ float ex2(float x) {
    float y; asm("ex2.approx.ftz.f32 %0, %1;" : "=f"(y) : "f"(x)); return y;
}
__device__ __forceinline__ void cpasync16(uint32_t saddr, const void* g) {
    asm volatile("cp.async.cg.shared.global [%0], [%1], 16;" :: "r"(saddr), "l"(g));
}
#define CP_COMMIT() asm volatile("cp.async.commit_group;" ::: "memory")
#define CP_WAIT(n)  asm volatile("cp.async.wait_group %0;" :: "n"(n) : "memory")

__device__ __forceinline__ void mma_tf32(float* d, const uint32_t* a, const uint32_t* b) {
    asm volatile(
        "mma.sync.aligned.m16n8k8.row.col.f32.tf32.tf32.f32 "
        "{%0,%1,%2,%3}, {%4,%5,%6,%7}, {%8,%9}, {%0,%1,%2,%3};"
        : "+f"(d[0]), "+f"(d[1]), "+f"(d[2]), "+f"(d[3])
        : "r"(a[0]), "r"(a[1]), "r"(a[2]), "r"(a[3]), "r"(b[0]), "r"(b[1]));
}

// ---------------------------------------------------------------------------
// Kernel 1: normalize rows, fold in sqrt(log2e/T), tf32-round, zero sums.
// ---------------------------------------------------------------------------
__global__ void prep_kernel(const float* __restrict__ emb,
                            const int*   __restrict__ labels,
                            const float* __restrict__ conf) {
    int row  = blockIdx.x * 8 + (threadIdx.x >> 5);
    int lane = threadIdx.x & 31;
    float4 v = ((const float4*)(emb + (size_t)row * D_))[lane];
    float ss = v.x*v.x + v.y*v.y + v.z*v.z + v.w*v.w;
    #pragma unroll
    for (int o = 16; o; o >>= 1) ss += __shfl_xor_sync(0xffffffffu, ss, o);
    const float SCALE = 3.7982826f;   // sqrt(log2(e) / 0.1)
    float s = SCALE / fmaxf(sqrtf(ss), 1e-12f);
    float4 w;
    w.x = tf32r(v.x * s); w.y = tf32r(v.y * s);
    w.z = tf32r(v.z * s); w.w = tf32r(v.w * s);
    ((float4*)(g_eTF + (size_t)row * D_))[lane] = w;
    if (lane == 0) {
        float c = conf[row];
        float sg = (c > 0.f) ? 1.f : ((c < 0.f) ? -1.f : 0.f);
        g_q[row] = sg * ((labels[row] == 1) ? 1.f : 2.f);
        g_pos[row] = 0.f;
        g_neg[row] = 0.f;
    }
}

// ---------------------------------------------------------------------------
// Kernel 2: tf32 mma.sync 128x128 tile GEMM over upper-triangular tile pairs,
// fused exp2/mask epilogue with row sums (and col sums on off-diagonal tiles).
// 512 threads = 16 warps in a 4x4 grid; each warp owns a 32x32 micro-tile.
// ---------------------------------------------------------------------------
__global__ void __launch_bounds__(512, 1) sim_kernel() {
    extern __shared__ char smem[];
    const uint32_t sb = smem_u32(smem);

    const int tid  = threadIdx.x;
    const int wid  = tid >> 5;
    const int lane = tid & 31;
    const int grp  = lane >> 2;     // 0..7
    const int qid  = lane & 3;      // 0..3
    const int wr   = wid >> 2;      // warp row 0..3 -> rows wr*32
    const int wc   = wid & 3;       // warp col 0..3 -> cols wc*32

    // Triangular decode of (ti, tj), ti <= tj
    int idx = blockIdx.x;
    int ti = (int)((2.0 * NT_ + 1.0 - sqrt((2.0 * NT_ + 1.0) * (2.0 * NT_ + 1.0) - 8.0 * idx)) * 0.5);
    #define FTRI(i) ((i) * (2 * NT_ - (i) + 1) / 2)
    while (ti > 0 && FTRI(ti) > idx) ti--;
    while (FTRI(ti + 1) <= idx) ti++;
    int tj = ti + (idx - FTRI(ti));
    const int i0 = ti * 128;
    const int j0 = tj * 128;
    const bool offdiag = (ti != tj);

    // Prefetch both 64-wide K chunks of A and B tiles via cp.async.
    {
        const char* srcA = (const char*)(g_eTF + (size_t)i0 * D_);
        const char* srcB = (const char*)(g_eTF + (size_t)j0 * D_);
        #pragma unroll
        for (int it = 0; it < 4; it++) {
            int t = tid + it * 512;          // 0..2047
            int row = t >> 4, kg = t & 15;   // kg: 16B group within 64 floats
            uint32_t doff = (uint32_t)(row * LDS_ + kg * 4) * 4u;
            size_t soff = ((size_t)row * D_ + kg * 4) * 4u;
            cpasync16(sb + OFF_A0 + doff, srcA + soff);
            cpasync16(sb + OFF_B0 + doff, srcB + soff);
        }
        CP_COMMIT();
        #pragma unroll
        for (int it = 0; it < 4; it++) {
            int t = tid + it * 512;
            int row = t >> 4, kg = t & 15;
            uint32_t doff = (uint32_t)(row * LDS_ + kg * 4) * 4u;
            size_t soff = ((size_t)row * D_ + 64 + kg * 4) * 4u;
            cpasync16(sb + OFF_A1 + doff, srcA + soff);
            cpasync16(sb + OFF_B1 + doff, srcB + soff);
        }
        CP_COMMIT();
    }
    // Stage class codes while fills are in flight.
    float* qi_sh = (float*)(smem + OFF_QI);
    float* qj_sh = (float*)(smem + OFF_QJ);
    if (tid < 128)                 qi_sh[tid]       = g_q[i0 + tid];
    else if (tid < 256)            qj_sh[tid - 128] = g_q[j0 + (tid - 128)];

    float acc[2][4][4] = {};   // [mt][nt][4]

    const uint32_t* As[2] = { (const uint32_t*)(smem + OFF_A0), (const uint32_t*)(smem + OFF_A1) };
    const uint32_t* Bs[2] = { (const uint32_t*)(smem + OFF_B0), (const uint32_t*)(smem + OFF_B1) };

    CP_WAIT(1);
    __syncthreads();

    #pragma unroll
    for (int ch = 0; ch < 2; ch++) {
        if (ch == 1) { CP_WAIT(0); __syncthreads(); }
        const uint32_t* A = As[ch];
        const uint32_t* B = Bs[ch];
        #pragma unroll
        for (int ks = 0; ks < 8; ks++) {
            const int k0 = ks * 8 + qid;
            uint32_t af[2][4], bf[4][2];
            #pragma unroll
            for (int mt = 0; mt < 2; mt++) {
                int rb = wr * 32 + mt * 16 + grp;
                af[mt][0] = A[rb * LDS_ + k0];
                af[mt][1] = A[(rb + 8) * LDS_ + k0];
                af[mt][2] = A[rb * LDS_ + k0 + 4];
                af[mt][3] = A[(rb + 8) * LDS_ + k0 + 4];
            }
            #pragma unroll
            for (int nt = 0; nt < 4; nt++) {
                int cb = wc * 32 + nt * 8 + grp;
                bf[nt][0] = B[cb * LDS_ + k0];
                bf[nt][1] = B[cb * LDS_ + k0 + 4];
            }
            #pragma unroll
            for (int mt = 0; mt < 2; mt++)
                #pragma unroll
                for (int nt = 0; nt < 4; nt++)
                    mma_tf32(acc[mt][nt], af[mt], bf[nt]);
        }
    }

    // ---------------- Epilogue ----------------
    // Rows of this thread: wr*32 + mt*16 + grp (+8). Cols: wc*32 + nt*8 + 2*qid (+1).
    float fi[4], fj[8];
    #pragma unroll
    for (int mt = 0; mt < 2; mt++) {
        fi[mt * 2 + 0] = qi_sh[wr * 32 + mt * 16 + grp];
        fi[mt * 2 + 1] = qi_sh[wr * 32 + mt * 16 + grp + 8];
    }
    #pragma unroll
    for (int nt = 0; nt < 4; nt++) {
        fj[nt * 2 + 0] = qj_sh[wc * 32 + nt * 8 + 2 * qid];
        fj[nt * 2 + 1] = qj_sh[wc * 32 + nt * 8 + 2 * qid + 1];
    }

    float ps[4] = {}, ns[4] = {};        // per-row partials (this warp's 32-col strip)
    float cp_[8] = {}, cn_[8] = {};      // per-col partials (this warp's 32-row strip)

    #pragma unroll
    for (int mt = 0; mt < 2; mt++) {
        int gi_a = i0 + wr * 32 + mt * 16 + grp;
        int gi_b = gi_a + 8;
        #pragma unroll
        for (int nt = 0; nt < 4; nt++) {
            int gj0 = j0 + wc * 32 + nt * 8 + 2 * qid;
            #pragma unroll
            for (int v = 0; v < 4; v++) {
                int gi = (v < 2) ? gi_a : gi_b;
                int gj = gj0 + (v & 1);
                float ex = ex2(acc[mt][nt][v]);
                float p  = fi[mt * 2 + (v >> 1)] * fj[nt * 2 + (v & 1)];
                bool neg = (p == 2.f);
                bool pos = (p == 1.f || p == 4.f) && (gi != gj);
                float pe = pos ? ex : 0.f;
                float ne = neg ? ex : 0.f;
                ps[mt * 2 + (v >> 1)] += pe;
                ns[mt * 2 + (v >> 1)] += ne;
                cp_[nt * 2 + (v & 1)] += pe;
                cn_[nt * 2 + (v & 1)] += ne;
            }
        }
    }

    // Row reduce across the 4 col-phases (qid): shfl_xor 1, 2.
    #pragma unroll
    for (int r = 0; r < 4; r++) {
        #pragma unroll
        for (int o = 1; o <= 2; o <<= 1) {
            ps[r] += __shfl_xor_sync(0xffffffffu, ps[r], o);
            ns[r] += __shfl_xor_sync(0xffffffffu, ns[r], o);
        }
    }
    if (qid == 0) {
        #pragma unroll
        for (int r = 0; r < 4; r++) {
            int gi = i0 + wr * 32 + (r >> 1) * 16 + grp + (r & 1) * 8;
            atomicAdd(&g_pos[gi], ps[r]);
            atomicAdd(&g_neg[gi], ns[r]);
        }
    }

    // Col reduce across the 8 row-groups (grp): shfl_xor 4, 8, 16. Off-diag only.
    if (offdiag) {
        #pragma unroll
        for (int c = 0; c < 8; c++) {
            #pragma unroll
            for (int o = 4; o <= 16; o <<= 1) {
                cp_[c] += __shfl_xor_sync(0xffffffffu, cp_[c], o);
                cn_[c] += __shfl_xor_sync(0xffffffffu, cn_[c], o);
            }
        }
        if (grp == 0) {
            #pragma unroll
            for (int c = 0; c < 8; c++) {
                int gj = j0 + wc * 32 + (c >> 1) * 8 + 2 * qid + (c & 1);
                atomicAdd(&g_pos[gj], cp_[c]);
                atomicAdd(&g_neg[gj], cn_[c]);
            }
        }
    }
}

// ---------------------------------------------------------------------------
// Kernel 3: final loss reduction over rows.
// ---------------------------------------------------------------------------
__global__ void loss_kernel(float* __restrict__ out, int B) {
    __shared__ float ssum[256];
    __shared__ float scnt[256];
    int tid = threadIdx.x;
    float tot = 0.f, cnt = 0.f;
    for (int i = tid; i < B; i += 256) {
        float p = g_pos[i], n = g_neg[i];
        if (p > 0.f && n > 0.f) {
            tot += -logf(p / (p + n + 1e-8f));
            cnt += 1.f;
        }
    }
    ssum[tid] = tot; scnt[tid] = cnt;
    __syncthreads();
    #pragma unroll
    for (int s = 128; s > 0; s >>= 1) {
        if (tid < s) { ssum[tid] += ssum[tid + s]; scnt[tid] += scnt[tid + s]; }
        __syncthreads();
    }
    if (tid == 0) {
        float c = scnt[0];
        out[0] = (c > 0.f) ? (ssum[0] / c) : 0.f;
    }
}

extern "C" void kernel_launch(void* const* d_in, const int* in_sizes, int n_in,
                              void* d_out, int out_size) {
    const float* emb    = (const float*)d_in[0];
    const int*   labels = (const int*)  d_in[1];
    const float* conf   = (const float*)d_in[2];
    int B = in_sizes[1];   // 8192
    (void)n_in; (void)out_size;

    cudaFuncSetAttribute(sim_kernel, cudaFuncAttributeMaxDynamicSharedMemorySize, SMEM_BYTES);

    prep_kernel<<<B / 8, 256>>>(emb, labels, conf);
    sim_kernel<<<NPAIRS, 512, SMEM_BYTES>>>();
    loss_kernel<<<1, 256>>>((float*)d_out, B);
}

// round 4
// speedup vs baseline: 4.2385x; 1.3013x over previous
#include <cuda_runtime.h>
#include <cuda_fp16.h>
#include <math.h>
#include <stdint.h>

#define B_ 8192
#define D_ 128
#define NT_ 64                            // number of 128-row tiles
#define NPAIRS ((NT_ * (NT_ + 1)) / 2)    // 2080 upper-triangular tile pairs

// Smem tiles: 128 rows x 128 halves (256B) padded to 272B (stride ≡ 16 mod 128
// => ldmatrix 8-row groups hit banks 0,4,...,28: conflict-free).
#define ROWB 272
#define TILE_BYTES (128 * ROWB)           // 34816
#define OFF_A 0
#define OFF_B TILE_BYTES
#define OFF_QI (2 * TILE_BYTES)           // 69632
#define OFF_QJ (OFF_QI + 512)
#define SMEM_BYTES (OFF_QJ + 512)         // 70656

__device__ __align__(16) __half g_eH[B_ * D_];  // scaled by sqrt(log2e/T), fp16
__device__ float g_q[B_];    // class code: sign(conf) * (label==1 ? 1 : 2)
__device__ float g_pos[B_];
__device__ float g_neg[B_];

// ---------------------------------------------------------------------------
__device__ __forceinline__ uint32_t smem_u32(const void* p) {
    uint32_t a;
    asm("{ .reg .u64 t; cvta.to.shared.u64 t, %1; cvt.u32.u64 %0, t; }" : "=r"(a) : "l"(p));
    return a;
}
__device__ __forceinline__ float ex2(float x) {
    float y; asm("ex2.approx.ftz.f32 %0, %1;" : "=f"(y) : "f"(x)); return y;
}
__device__ __forceinline__ void cpasync16(uint32_t saddr, const void* g) {
    asm volatile("cp.async.cg.shared.global [%0], [%1], 16;" :: "r"(saddr), "l"(g));
}
#define CP_COMMIT() asm volatile("cp.async.commit_group;" ::: "memory")
#define CP_WAIT0()  asm volatile("cp.async.wait_group 0;" ::: "memory")

__device__ __forceinline__ void ldm_x4(uint32_t* r, uint32_t addr) {
    asm volatile("ldmatrix.sync.aligned.m8n8.x4.shared.b16 {%0,%1,%2,%3}, [%4];"
                 : "=r"(r[0]), "=r"(r[1]), "=r"(r[2]), "=r"(r[3]) : "r"(addr));
}
__device__ __forceinline__ void mma_f16(float* d, const uint32_t* a, const uint32_t* b) {
    asm volatile(
        "mma.sync.aligned.m16n8k16.row.col.f32.f16.f16.f32 "
        "{%0,%1,%2,%3}, {%4,%5,%6,%7}, {%8,%9}, {%0,%1,%2,%3};"
        : "+f"(d[0]), "+f"(d[1]), "+f"(d[2]), "+f"(d[3])
        : "r"(a[0]), "r"(a[1]), "r"(a[2]), "r"(a[3]), "r"(b[0]), "r"(b[1]));
}

// ---------------------------------------------------------------------------
// Kernel 1: normalize rows, fold in sqrt(log2e/T), fp16-round, zero sums.
// ---------------------------------------------------------------------------
__global__ void prep_kernel(const float* __restrict__ emb,
                            const int*   __restrict__ labels,
                            const float* __restrict__ conf) {
    int row  = blockIdx.x * 8 + (threadIdx.x >> 5);
    int lane = threadIdx.x & 31;
    float4 v = ((const float4*)(emb + (size_t)row * D_))[lane];
    float ss = v.x*v.x + v.y*v.y + v.z*v.z + v.w*v.w;
    #pragma unroll
    for (int o = 16; o; o >>= 1) ss += __shfl_xor_sync(0xffffffffu, ss, o);
    const float SCALE = 3.7982826f;   // sqrt(log2(e) / 0.1)
    float s = SCALE / fmaxf(sqrtf(ss), 1e-12f);
    __half2 h0 = __floats2half2_rn(v.x * s, v.y * s);
    __half2 h1 = __floats2half2_rn(v.z * s, v.w * s);
    uint2 pk = { *(uint32_t*)&h0, *(uint32_t*)&h1 };
    ((uint2*)(g_eH + (size_t)row * D_))[lane] = pk;
    if (lane == 0) {
        float c = conf[row];
        float sg = (c > 0.f) ? 1.f : ((c < 0.f) ? -1.f : 0.f);
        g_q[row] = sg * ((labels[row] == 1) ? 1.f : 2.f);
        g_pos[row] = 0.f;
        g_neg[row] = 0.f;
    }
}

// ---------------------------------------------------------------------------
// Kernel 2: fp16 mma.sync 128x128x128 tile over upper-triangular tile pairs,
// fused exp2/mask epilogue, row sums (+ col sums on off-diagonal tiles).
// 512 threads = 16 warps (4x4); each warp owns a 32x32 micro-tile.
// ---------------------------------------------------------------------------
__global__ void __launch_bounds__(512, 1) sim_kernel() {
    extern __shared__ char smem[];
    const uint32_t sb = smem_u32(smem);

    const int tid  = threadIdx.x;
    const int wid  = tid >> 5;
    const int lane = tid & 31;
    const int grp  = lane >> 2;     // 0..7
    const int qid  = lane & 3;      // 0..3
    const int wr   = wid >> 2;      // warp row
    const int wc   = wid & 3;       // warp col

    // Triangular decode of (ti, tj), ti <= tj
    int idx = blockIdx.x;
    int ti = (int)((2.0 * NT_ + 1.0 - sqrt((2.0 * NT_ + 1.0) * (2.0 * NT_ + 1.0) - 8.0 * idx)) * 0.5);
    #define FTRI(i) ((i) * (2 * NT_ - (i) + 1) / 2)
    while (ti > 0 && FTRI(ti) > idx) ti--;
    while (FTRI(ti + 1) <= idx) ti++;
    int tj = ti + (idx - FTRI(ti));
    const int i0 = ti * 128;
    const int j0 = tj * 128;
    const bool offdiag = (ti != tj);

    // Fill A and B tiles (full K resident): 2048 x 16B each, 8 cp.async/thread.
    {
        const char* srcA = (const char*)(g_eH + (size_t)i0 * D_);
        const char* srcB = (const char*)(g_eH + (size_t)j0 * D_);
        #pragma unroll
        for (int it = 0; it < 4; it++) {
            int t = tid + it * 512;          // 0..2047
            int row = t >> 4, kg = t & 15;   // 16B group within 256B row
            uint32_t doff = (uint32_t)(row * ROWB + kg * 16);
            size_t soff = (size_t)row * 256 + kg * 16;
            cpasync16(sb + OFF_A + doff, srcA + soff);
            cpasync16(sb + OFF_B + doff, srcB + soff);
        }
        CP_COMMIT();
    }
    // Stage class codes while fills are in flight.
    float* qi_sh = (float*)(smem + OFF_QI);
    float* qj_sh = (float*)(smem + OFF_QJ);
    if (tid < 128)       qi_sh[tid]       = g_q[i0 + tid];
    else if (tid < 256)  qj_sh[tid - 128] = g_q[j0 + (tid - 128)];

    float acc[2][4][4] = {};   // [mt][nt][4]

    // ldmatrix lane-address components (constant across ksteps):
    // A (x4): row = R0 + (lane&15), koff16 = (lane>>4)*16
    // B (x4): row(col) = C0 + ((lane>>4)*8) + (lane&7), koff16 = ((lane>>3)&1)*16
    const uint32_t aAddr0 = sb + OFF_A + (uint32_t)((wr * 32 + (lane & 15)) * ROWB) + (uint32_t)((lane >> 4) * 16);
    const uint32_t bAddr0 = sb + OFF_B + (uint32_t)((wc * 32 + ((lane >> 4) & 1) * 8 + (lane & 7)) * ROWB)
                                       + (uint32_t)(((lane >> 3) & 1) * 16);

    CP_WAIT0();
    __syncthreads();

    #pragma unroll
    for (int ks = 0; ks < 8; ks++) {
        const uint32_t ko = (uint32_t)(ks * 32);   // 16 halves = 32B per kstep
        uint32_t af[2][4], bf[2][4];
        ldm_x4(af[0], aAddr0 + ko);                 // rows wr*32..+15
        ldm_x4(af[1], aAddr0 + (uint32_t)(16 * ROWB) + ko);   // rows +16..+31
        ldm_x4(bf[0], bAddr0 + ko);                 // cols wc*32..+15
        ldm_x4(bf[1], bAddr0 + (uint32_t)(16 * ROWB) + ko);   // cols +16..+31
        #pragma unroll
        for (int mt = 0; mt < 2; mt++)
            #pragma unroll
            for (int nt = 0; nt < 4; nt++)
                mma_f16(acc[mt][nt], af[mt], &bf[nt >> 1][(nt & 1) * 2]);
    }

    // ---------------- Epilogue ----------------
    // Thread rows: wr*32 + mt*16 + grp (+8). Cols: wc*32 + nt*8 + 2*qid (+1).
    float fi[4], fj[8];
    #pragma unroll
    for (int mt = 0; mt < 2; mt++) {
        fi[mt * 2 + 0] = qi_sh[wr * 32 + mt * 16 + grp];
        fi[mt * 2 + 1] = qi_sh[wr * 32 + mt * 16 + grp + 8];
    }
    #pragma unroll
    for (int nt = 0; nt < 4; nt++) {
        fj[nt * 2 + 0] = qj_sh[wc * 32 + nt * 8 + 2 * qid];
        fj[nt * 2 + 1] = qj_sh[wc * 32 + nt * 8 + 2 * qid + 1];
    }

    float ps[4] = {}, ns[4] = {};
    float cp_[8] = {}, cn_[8] = {};

    #pragma unroll
    for (int mt = 0; mt < 2; mt++) {
        int gi_a = i0 + wr * 32 + mt * 16 + grp;
        int gi_b = gi_a + 8;
        #pragma unroll
        for (int nt = 0; nt < 4; nt++) {
            int gj0 = j0 + wc * 32 + nt * 8 + 2 * qid;
            #pragma unroll
            for (int v = 0; v < 4; v++) {
                int gi = (v < 2) ? gi_a : gi_b;
                int gj = gj0 + (v & 1);
                float ex = ex2(acc[mt][nt][v]);
                float p  = fi[mt * 2 + (v >> 1)] * fj[nt * 2 + (v & 1)];
                bool neg = (p == 2.f);
                bool pos = (p == 1.f || p == 4.f) && (gi != gj);
                float pe = pos ? ex : 0.f;
                float ne = neg ? ex : 0.f;
                ps[mt * 2 + (v >> 1)] += pe;
                ns[mt * 2 + (v >> 1)] += ne;
                cp_[nt * 2 + (v & 1)] += pe;
                cn_[nt * 2 + (v & 1)] += ne;
            }
        }
    }

    // Row reduce across qid (shfl 1,2).
    #pragma unroll
    for (int r = 0; r < 4; r++) {
        #pragma unroll
        for (int o = 1; o <= 2; o <<= 1) {
            ps[r] += __shfl_xor_sync(0xffffffffu, ps[r], o);
            ns[r] += __shfl_xor_sync(0xffffffffu, ns[r], o);
        }
    }
    if (qid == 0) {
        #pragma unroll
        for (int r = 0; r < 4; r++) {
            int gi = i0 + wr * 32 + (r >> 1) * 16 + grp + (r & 1) * 8;
            atomicAdd(&g_pos[gi], ps[r]);
            atomicAdd(&g_neg[gi], ns[r]);
        }
    }

    // Col reduce across grp (shfl 4,8,16). Off-diagonal tiles only.
    if (offdiag) {
        #pragma unroll
        for (int c = 0; c < 8; c++) {
            #pragma unroll
            for (int o = 4; o <= 16; o <<= 1) {
                cp_[c] += __shfl_xor_sync(0xffffffffu, cp_[c], o);
                cn_[c] += __shfl_xor_sync(0xffffffffu, cn_[c], o);
            }
        }
        if (grp == 0) {
            #pragma unroll
            for (int c = 0; c < 8; c++) {
                int gj = j0 + wc * 32 + (c >> 1) * 8 + 2 * qid + (c & 1);
                atomicAdd(&g_pos[gj], cp_[c]);
                atomicAdd(&g_neg[gj], cn_[c]);
            }
        }
    }
}

// ---------------------------------------------------------------------------
// Kernel 3: final loss reduction over rows.
// ---------------------------------------------------------------------------
__global__ void loss_kernel(float* __restrict__ out, int B) {
    __shared__ float ssum[256];
    __shared__ float scnt[256];
    int tid = threadIdx.x;
    float tot = 0.f, cnt = 0.f;
    for (int i = tid; i < B; i += 256) {
        float p = g_pos[i], n = g_neg[i];
        if (p > 0.f && n > 0.f) {
            tot += -logf(p / (p + n + 1e-8f));
            cnt += 1.f;
        }
    }
    ssum[tid] = tot; scnt[tid] = cnt;
    __syncthreads();
    #pragma unroll
    for (int s = 128; s > 0; s >>= 1) {
        if (tid < s) { ssum[tid] += ssum[tid + s]; scnt[tid] += scnt[tid + s]; }
        __syncthreads();
    }
    if (tid == 0) {
        float c = scnt[0];
        out[0] = (c > 0.f) ? (ssum[0] / c) : 0.f;
    }
}

extern "C" void kernel_launch(void* const* d_in, const int* in_sizes, int n_in,
                              void* d_out, int out_size) {
    const float* emb    = (const float*)d_in[0];
    const int*   labels = (const int*)  d_in[1];
    const float* conf   = (const float*)d_in[2];
    int B = in_sizes[1];   // 8192
    (void)n_in; (void)out_size;

    cudaFuncSetAttribute(sim_kernel, cudaFuncAttributeMaxDynamicSharedMemorySize, SMEM_BYTES);

    prep_kernel<<<B / 8, 256>>>(emb, labels, conf);
    sim_kernel<<<NPAIRS, 512, SMEM_BYTES>>>();
    loss_kernel<<<1, 256>>>((float*)d_out, B);
}

// round 5
// speedup vs baseline: 4.4045x; 1.0392x over previous
#include <cuda_runtime.h>
#include <cuda_fp16.h>
#include <math.h>
#include <stdint.h>

#define B_ 8192
#define D_ 128
#define NT_ 64                            // number of 128-row tiles
#define NPAIRS ((NT_ * (NT_ + 1)) / 2)    // 2080 upper-triangular tile pairs
#define NSM 148

// Smem tiles: 128 rows x 128 halves (256B) padded to 272B (stride ≡ 16 mod 128
// => ldmatrix 8-row groups hit banks 0,4,...,28: conflict-free). Double buffered.
#define ROWB 272
#define TILE_BYTES (128 * ROWB)           // 34816
#define OFF_A0 0
#define OFF_B0 TILE_BYTES
#define OFF_A1 (2 * TILE_BYTES)
#define OFF_B1 (3 * TILE_BYTES)
#define OFF_Q  (4 * TILE_BYTES)           // qi0[128] qj0[128] qi1[128] qj1[128]
#define SMEM_BYTES (OFF_Q + 4 * 128 * 4)  // 141312

__device__ __align__(16) __half g_eH[B_ * D_];  // scaled by sqrt(log2e/T), fp16
__device__ float g_q[B_];    // class code: sign(conf) * (label==1 ? 1 : 2)
__device__ float g_pos[B_];
__device__ float g_neg[B_];

// ---------------------------------------------------------------------------
__device__ __forceinline__ uint32_t smem_u32(const void* p) {
    uint32_t a;
    asm("{ .reg .u64 t; cvta.to.shared.u64 t, %1; cvt.u32.u64 %0, t; }" : "=r"(a) : "l"(p));
    return a;
}
__device__ __forceinline__ float ex2(float x) {
    float y; asm("ex2.approx.ftz.f32 %0, %1;" : "=f"(y) : "f"(x)); return y;
}
__device__ __forceinline__ void cpasync16(uint32_t saddr, const void* g) {
    asm volatile("cp.async.cg.shared.global [%0], [%1], 16;" :: "r"(saddr), "l"(g));
}
#define CP_COMMIT() asm volatile("cp.async.commit_group;" ::: "memory")
#define CP_WAIT0()  asm volatile("cp.async.wait_group 0;" ::: "memory")

__device__ __forceinline__ void ldm_x4(uint32_t* r, uint32_t addr) {
    asm volatile("ldmatrix.sync.aligned.m8n8.x4.shared.b16 {%0,%1,%2,%3}, [%4];"
                 : "=r"(r[0]), "=r"(r[1]), "=r"(r[2]), "=r"(r[3]) : "r"(addr));
}
__device__ __forceinline__ void mma_f16(float* d, const uint32_t* a, const uint32_t* b) {
    asm volatile(
        "mma.sync.aligned.m16n8k16.row.col.f32.f16.f16.f32 "
        "{%0,%1,%2,%3}, {%4,%5,%6,%7}, {%8,%9}, {%0,%1,%2,%3};"
        : "+f"(d[0]), "+f"(d[1]), "+f"(d[2]), "+f"(d[3])
        : "r"(a[0]), "r"(a[1]), "r"(a[2]), "r"(a[3]), "r"(b[0]), "r"(b[1]));
}

// Triangular decode: idx -> (ti, tj), ti <= tj
__device__ __forceinline__ void tri_decode(int idx, int& ti, int& tj) {
    int t = (int)((2.0 * NT_ + 1.0 - sqrt((2.0 * NT_ + 1.0) * (2.0 * NT_ + 1.0) - 8.0 * idx)) * 0.5);
    #define FTRI(i) ((i) * (2 * NT_ - (i) + 1) / 2)
    while (t > 0 && FTRI(t) > idx) t--;
    while (FTRI(t + 1) <= idx) t++;
    ti = t;
    tj = t + (idx - FTRI(t));
}

// ---------------------------------------------------------------------------
// Kernel 1: normalize rows, fold in sqrt(log2e/T), fp16-round, zero sums.
// ---------------------------------------------------------------------------
__global__ void prep_kernel(const float* __restrict__ emb,
                            const int*   __restrict__ labels,
                            const float* __restrict__ conf) {
    int row  = blockIdx.x * 8 + (threadIdx.x >> 5);
    int lane = threadIdx.x & 31;
    float4 v = ((const float4*)(emb + (size_t)row * D_))[lane];
    float ss = v.x*v.x + v.y*v.y + v.z*v.z + v.w*v.w;
    #pragma unroll
    for (int o = 16; o; o >>= 1) ss += __shfl_xor_sync(0xffffffffu, ss, o);
    const float SCALE = 3.7982826f;   // sqrt(log2(e) / 0.1)
    float s = SCALE / fmaxf(sqrtf(ss), 1e-12f);
    __half2 h0 = __floats2half2_rn(v.x * s, v.y * s);
    __half2 h1 = __floats2half2_rn(v.z * s, v.w * s);
    uint2 pk = { *(uint32_t*)&h0, *(uint32_t*)&h1 };
    ((uint2*)(g_eH + (size_t)row * D_))[lane] = pk;
    if (lane == 0) {
        float c = conf[row];
        float sg = (c > 0.f) ? 1.f : ((c < 0.f) ? -1.f : 0.f);
        g_q[row] = sg * ((labels[row] == 1) ? 1.f : 2.f);
        g_pos[row] = 0.f;
        g_neg[row] = 0.f;
    }
}

// ---------------------------------------------------------------------------
// Kernel 2: persistent-CTA fp16 mma.sync 128x128x128 tiles over the upper
// triangle, cross-tile double-buffered cp.async fills, fused exp2/mask
// epilogue, row sums (+ col sums on off-diagonal tiles).
// 512 threads = 16 warps (4x4); each warp owns a 32x32 micro-tile.
// ---------------------------------------------------------------------------
__global__ void __launch_bounds__(512, 1) sim_kernel() {
    extern __shared__ char smem[];
    const uint32_t sb = smem_u32(smem);

    const int tid  = threadIdx.x;
    const int wid  = tid >> 5;
    const int lane = tid & 31;
    const int grp  = lane >> 2;     // 0..7
    const int qid  = lane & 3;      // 0..3
    const int wr   = wid >> 2;      // warp row
    const int wc   = wid & 3;       // warp col

    float* qsm = (float*)(smem + OFF_Q);   // [buf][2][128]

    // Per-thread fill indices (8 x 16B chunks per tile buffer).
    int frow[4], fkg[4];
    #pragma unroll
    for (int it = 0; it < 4; it++) {
        int t = tid + it * 512;
        frow[it] = t >> 4;
        fkg[it]  = t & 15;
    }

    // Fill helper via macro-ish lambda (A and B of a tile pair into buffer b).
    auto issue_fill = [&](int ti, int tj, int b) {
        const char* srcA = (const char*)(g_eH + (size_t)(ti * 128) * D_);
        const char* srcB = (const char*)(g_eH + (size_t)(tj * 128) * D_);
        uint32_t offA = (b ? OFF_A1 : OFF_A0);
        uint32_t offB = (b ? OFF_B1 : OFF_B0);
        #pragma unroll
        for (int it = 0; it < 4; it++) {
            uint32_t doff = (uint32_t)(frow[it] * ROWB + fkg[it] * 16);
            size_t soff = (size_t)frow[it] * 256 + (size_t)fkg[it] * 16;
            cpasync16(sb + offA + doff, srcA + soff);
            cpasync16(sb + offB + doff, srcB + soff);
        }
        CP_COMMIT();
        // class codes (regular stores; ordered by next syncthreads)
        if (tid < 128)       qsm[b * 256 + tid]       = g_q[ti * 128 + tid];
        else if (tid < 256)  qsm[b * 256 + tid]       = g_q[tj * 128 + (tid - 128)];
    };

    // ldmatrix lane-address components (constant; add buffer base per tile).
    const uint32_t aRel = (uint32_t)((wr * 32 + (lane & 15)) * ROWB) + (uint32_t)((lane >> 4) * 16);
    const uint32_t bRel = (uint32_t)((wc * 32 + ((lane >> 4) & 1) * 8 + (lane & 7)) * ROWB)
                        + (uint32_t)(((lane >> 3) & 1) * 16);

    // Prologue: fill first tile into buffer 0.
    {
        int ti, tj;
        tri_decode(blockIdx.x, ti, tj);
        issue_fill(ti, tj, 0);
    }

    int b = 0;
    for (int t = blockIdx.x; t < NPAIRS; t += NSM, b ^= 1) {
        CP_WAIT0();
        __syncthreads();   // tile t visible; all warps done with buffer b^1

        int tn = t + NSM;
        if (tn < NPAIRS) {
            int tin, tjn;
            tri_decode(tn, tin, tjn);
            issue_fill(tin, tjn, b ^ 1);
        }

        int ti, tj;
        tri_decode(t, ti, tj);
        const int i0 = ti * 128;
        const int j0 = tj * 128;
        const bool offdiag = (ti != tj);

        const uint32_t aAddr0 = sb + (b ? OFF_A1 : OFF_A0) + aRel;
        const uint32_t bAddr0 = sb + (b ? OFF_B1 : OFF_B0) + bRel;

        float acc[2][4][4] = {};   // [mt][nt][4]

        #pragma unroll
        for (int ks = 0; ks < 8; ks++) {
            const uint32_t ko = (uint32_t)(ks * 32);   // 16 halves = 32B per kstep
            uint32_t af[2][4], bf[2][4];
            ldm_x4(af[0], aAddr0 + ko);
            ldm_x4(af[1], aAddr0 + (uint32_t)(16 * ROWB) + ko);
            ldm_x4(bf[0], bAddr0 + ko);
            ldm_x4(bf[1], bAddr0 + (uint32_t)(16 * ROWB) + ko);
            #pragma unroll
            for (int mt = 0; mt < 2; mt++)
                #pragma unroll
                for (int nt = 0; nt < 4; nt++)
                    mma_f16(acc[mt][nt], af[mt], &bf[nt >> 1][(nt & 1) * 2]);
        }

        // ---------------- Epilogue ----------------
        const float* qi_sh = qsm + b * 256;
        const float* qj_sh = qi_sh + 128;
        float fi[4], fj[8];
        #pragma unroll
        for (int mt = 0; mt < 2; mt++) {
            fi[mt * 2 + 0] = qi_sh[wr * 32 + mt * 16 + grp];
            fi[mt * 2 + 1] = qi_sh[wr * 32 + mt * 16 + grp + 8];
        }
        #pragma unroll
        for (int nt = 0; nt < 4; nt++) {
            fj[nt * 2 + 0] = qj_sh[wc * 32 + nt * 8 + 2 * qid];
            fj[nt * 2 + 1] = qj_sh[wc * 32 + nt * 8 + 2 * qid + 1];
        }

        float ps[4] = {}, ns[4] = {};
        float cp_[8] = {}, cn_[8] = {};

        #pragma unroll
        for (int mt = 0; mt < 2; mt++) {
            int gi_a = i0 + wr * 32 + mt * 16 + grp;
            int gi_b = gi_a + 8;
            #pragma unroll
            for (int nt = 0; nt < 4; nt++) {
                int gj0 = j0 + wc * 32 + nt * 8 + 2 * qid;
                #pragma unroll
                for (int v = 0; v < 4; v++) {
                    int gi = (v < 2) ? gi_a : gi_b;
                    int gj = gj0 + (v & 1);
                    float ex = ex2(acc[mt][nt][v]);
                    float p  = fi[mt * 2 + (v >> 1)] * fj[nt * 2 + (v & 1)];
                    bool neg = (p == 2.f);
                    bool pos = (p == 1.f || p == 4.f) && (gi != gj);
                    float pe = pos ? ex : 0.f;
                    float ne = neg ? ex : 0.f;
                    ps[mt * 2 + (v >> 1)] += pe;
                    ns[mt * 2 + (v >> 1)] += ne;
                    cp_[nt * 2 + (v & 1)] += pe;
                    cn_[nt * 2 + (v & 1)] += ne;
                }
            }
        }

        // Row reduce across qid (shfl 1,2).
        #pragma unroll
        for (int r = 0; r < 4; r++) {
            #pragma unroll
            for (int o = 1; o <= 2; o <<= 1) {
                ps[r] += __shfl_xor_sync(0xffffffffu, ps[r], o);
                ns[r] += __shfl_xor_sync(0xffffffffu, ns[r], o);
            }
        }
        if (qid == 0) {
            #pragma unroll
            for (int r = 0; r < 4; r++) {
                int gi = i0 + wr * 32 + (r >> 1) * 16 + grp + (r & 1) * 8;
                atomicAdd(&g_pos[gi], ps[r]);
                atomicAdd(&g_neg[gi], ns[r]);
            }
        }

        // Col reduce across grp (shfl 4,8,16). Off-diagonal tiles only.
        if (offdiag) {
            #pragma unroll
            for (int c = 0; c < 8; c++) {
                #pragma unroll
                for (int o = 4; o <= 16; o <<= 1) {
                    cp_[c] += __shfl_xor_sync(0xffffffffu, cp_[c], o);
                    cn_[c] += __shfl_xor_sync(0xffffffffu, cn_[c], o);
                }
            }
            if (grp == 0) {
                #pragma unroll
                for (int c = 0; c < 8; c++) {
                    int gj = j0 + wc * 32 + (c >> 1) * 8 + 2 * qid + (c & 1);
                    atomicAdd(&g_pos[gj], cp_[c]);
                    atomicAdd(&g_neg[gj], cn_[c]);
                }
            }
        }
    }
}

// ---------------------------------------------------------------------------
// Kernel 3: final loss reduction over rows.
// ---------------------------------------------------------------------------
__global__ void loss_kernel(float* __restrict__ out, int B) {
    __shared__ float ssum[1024];
    __shared__ float scnt[1024];
    int tid = threadIdx.x;
    float tot = 0.f, cnt = 0.f;
    for (int i = tid; i < B; i += 1024) {
        float p = g_pos[i], n = g_neg[i];
        if (p > 0.f && n > 0.f) {
            tot += -__logf(p / (p + n + 1e-8f));
            cnt += 1.f;
        }
    }
    ssum[tid] = tot; scnt[tid] = cnt;
    __syncthreads();
    #pragma unroll
    for (int s = 512; s > 0; s >>= 1) {
        if (tid < s) { ssum[tid] += ssum[tid + s]; scnt[tid] += scnt[tid + s]; }
        __syncthreads();
    }
    if (tid == 0) {
        float c = scnt[0];
        out[0] = (c > 0.f) ? (ssum[0] / c) : 0.f;
    }
}

extern "C" void kernel_launch(void* const* d_in, const int* in_sizes, int n_in,
                              void* d_out, int out_size) {
    const float* emb    = (const float*)d_in[0];
    const int*   labels = (const int*)  d_in[1];
    const float* conf   = (const float*)d_in[2];
    int B = in_sizes[1];   // 8192
    (void)n_in; (void)out_size;

    cudaFuncSetAttribute(sim_kernel, cudaFuncAttributeMaxDynamicSharedMemorySize, SMEM_BYTES);

    prep_kernel<<<B / 8, 256>>>(emb, labels, conf);
    sim_kernel<<<NSM, 512, SMEM_BYTES>>>();
    loss_kernel<<<1, 1024>>>((float*)d_out, B);
}